// round 17
// baseline (speedup 1.0000x reference)
#include <cuda_runtime.h>
#include <cuda_bf16.h>
#include <cuda_fp16.h>
#include <math.h>
#include <stdint.h>

// LSTM: T=1024, B=64, I=256, H=512, O=5
// out = [outputs (T*B*O) | h_T (B*H) | c_T (B*H)]

#define TT 1024
#define BB 64
#define II 256
#define HH 512
#define G4 2048
#define OO 5
#define REC_CTAS 128

// ---- device scratch ----
__device__ float g_xgT[(size_t)TT * G4 * BB];     // [T][4H][B]
__device__ float g_hsT[(size_t)TT * HH * BB];     // [T][H][B]
// Whh split-fp16 per rec-CTA tile: [(m*2+copy)*16 + r][512], r = gate*4+u
__device__ __half g_Awhh[128 * 2 * 16 * 512];
// h fp16 single plane, PADDED ldmatrix-ready, ping-pong: [pp 2][k 512][72]
__device__ __align__(16) __half g_hf16[2 * 512 * 72];
// Wih split-fp16: [copy 2][R 2048][k 256]
__device__ __half g_wih16[2 * 2048 * 256];
// x fp16 single plane, transposed per t: [t 1024][k 256][b 64]
__device__ __half g_x16[(size_t)1024 * 256 * 64];
__device__ unsigned g_bar_count;
__device__ volatile unsigned g_bar_gen;
__device__ unsigned g_flags[REC_CTAS];            // per-CTA step flags

__device__ __forceinline__ float sigf(float x) {
    return 1.0f / (1.0f + __expf(-x));
}
__device__ __forceinline__ float tanhfast(float x) {
    x = fminf(fmaxf(x, -15.0f), 15.0f);
    float e = __expf(2.0f * x);
    return __fdividef(e - 1.0f, e + 1.0f);
}

__device__ __forceinline__ void cpa16(uint32_t saddr, const void* gptr) {
    asm volatile("cp.async.cg.shared.global [%0], [%1], 16;"
                 :: "r"(saddr), "l"(gptr));
}
#define CP_COMMIT() asm volatile("cp.async.commit_group;")
#define CP_WAIT(n)  asm volatile("cp.async.wait_group %0;" :: "n"(n))

__device__ __forceinline__ void bulk_copy(uint32_t dst_smem, const void* src,
                                          uint32_t bytes, uint32_t mbar) {
    asm volatile(
        "cp.async.bulk.shared::cta.global.mbarrier::complete_tx::bytes "
        "[%0], [%1], %2, [%3];"
        :: "r"(dst_smem), "l"(src), "r"(bytes), "r"(mbar) : "memory");
}
#define MBAR_INIT(mb) \
    asm volatile("mbarrier.init.shared.b64 [%0], 1;" :: "r"(mb) : "memory")
#define MBAR_EXPECT_TX(mb, bytes) \
    asm volatile("mbarrier.arrive.expect_tx.shared.b64 _, [%0], %1;" \
                 :: "r"(mb), "r"(bytes) : "memory")
__device__ __forceinline__ void mbar_wait(uint32_t mb, uint32_t parity) {
    asm volatile(
        "{\n\t.reg .pred P;\n"
        "L_%=:\n\t"
        "mbarrier.try_wait.parity.acquire.cta.shared::cta.b64 P, [%0], %1;\n\t"
        "@P bra D_%=;\n\tbra L_%=;\n"
        "D_%=:\n\t}" :: "r"(mb), "r"(parity) : "memory");
}

#define LDSM_X4(r0,r1,r2,r3,addr) \
    asm volatile("ldmatrix.sync.aligned.m8n8.x4.shared.b16 {%0,%1,%2,%3}, [%4];" \
        : "=r"(r0),"=r"(r1),"=r"(r2),"=r"(r3) : "r"(addr))
#define LDSM_X2T(r0,r1,addr) \
    asm volatile("ldmatrix.sync.aligned.m8n8.x2.trans.shared.b16 {%0,%1}, [%2];" \
        : "=r"(r0),"=r"(r1) : "r"(addr))
#define MMAH16816(d0,d1,d2,d3,a0,a1,a2,a3,b0,b1) \
    asm volatile("mma.sync.aligned.m16n8k16.row.col.f32.f16.f16.f32 " \
        "{%0,%1,%2,%3}, {%4,%5,%6,%7}, {%8,%9}, {%0,%1,%2,%3};" \
        : "+f"(d0),"+f"(d1),"+f"(d2),"+f"(d3) \
        : "r"(a0),"r"(a1),"r"(a2),"r"(a3),"r"(b0),"r"(b1))

// Init-time barrier (atomic; used once)
__device__ __forceinline__ void grid_sync_init() {
    __syncthreads();
    if (threadIdx.x == 0) {
        unsigned old = g_bar_gen;
        __threadfence();
        unsigned t = atomicAdd(&g_bar_count, 1u);
        if (t == REC_CTAS - 1) {
            atomicExch(&g_bar_count, 0u);
            __threadfence();
            g_bar_gen = old + 1u;
        } else {
            while (g_bar_gen == old) { }
            __threadfence();
        }
    }
    __syncthreads();
}

// Per-step barrier: independent-address release stores + parallel acquire polls.
// Avoids the single-address atomic serialization (~27 cyc x 128 arrivals).
__device__ __forceinline__ void flag_sync(int m, unsigned val) {
    __syncthreads();
    if (threadIdx.x == 0)
        asm volatile("st.release.gpu.u32 [%0], %1;"
                     :: "l"(g_flags + m), "r"(val) : "memory");
    if (threadIdx.x < REC_CTAS) {
        unsigned v;
        do {
            asm volatile("ld.acquire.gpu.u32 %0, [%1];"
                         : "=r"(v) : "l"(g_flags + threadIdx.x) : "memory");
        } while (v < val);
    }
    __syncthreads();
}

// ============================================================================
// Kernel P1: Whh -> split-fp16 rec tiles (R = gate*512 + m*4 + u)
// ============================================================================
__global__ void prep_whh(const float* __restrict__ Whh) {
    int R = blockIdx.x;
    int gate = R >> 9, rem = R & 511;
    int m = rem >> 2, u = rem & 3;
    int r = gate * 4 + u;
    for (int k = threadIdx.x; k < HH; k += blockDim.x) {
        float w = Whh[(size_t)R * HH + k];
        __half hi = __float2half(w);
        __half lo = __float2half(w - __half2float(hi));
        g_Awhh[((size_t)(m * 2 + 0) * 16 + r) * HH + k] = hi;
        g_Awhh[((size_t)(m * 2 + 1) * 16 + r) * HH + k] = lo;
    }
}

// ============================================================================
// Kernel P2: Wih -> split-fp16 [copy][R][k]
// ============================================================================
__global__ void prep_wih(const float* __restrict__ Wih) {
    int R = blockIdx.x;
    for (int k = threadIdx.x; k < II; k += blockDim.x) {
        float w = Wih[(size_t)R * II + k];
        __half hi = __float2half(w);
        __half lo = __float2half(w - __half2float(hi));
        g_wih16[(size_t)R * II + k] = hi;
        g_wih16[(size_t)(2048 + R) * II + k] = lo;
    }
}

// ============================================================================
// Kernel P3: x[t] -> fp16 single plane, transposed [t][k][b]
// ============================================================================
__global__ void prep_x(const float* __restrict__ x) {
    __shared__ float xs[64 * 257];
    const int t = blockIdx.x, tid = threadIdx.x;
    for (int idx = tid; idx < 64 * 64; idx += 256) {
        int b = idx >> 6, i = idx & 63;
        float4 v = *(const float4*)(x + ((size_t)t * BB + b) * II + i * 4);
        xs[b * 257 + i*4 + 0] = v.x; xs[b * 257 + i*4 + 1] = v.y;
        xs[b * 257 + i*4 + 2] = v.z; xs[b * 257 + i*4 + 3] = v.w;
    }
    __syncthreads();
    __half* dst = g_x16 + (size_t)t * (256 * 64);
    for (int idx = tid; idx < 256 * 64; idx += 256) {
        int k = idx >> 6, b = idx & 63;
        dst[(size_t)k * 64 + b] = __float2half(xs[b * 257 + k]);
    }
}

// ============================================================================
// Kernel 1: pregemm via fp16 HMMA (unchanged from R16)
// ============================================================================
#define PG_ACOPY 18432
#define PG_AOFF  0
#define PG_BOFF  36864
#define PG_CHUNK 46080
#define PG_BIAS  (2 * PG_CHUNK)
#define PG_SMEM  (PG_BIAS + 512 + 256)

__device__ __forceinline__ void pg_stage(uint32_t sb, int buf, int mbG, int t,
                                         int kc, int tid) {
    uint32_t dst = sb + buf * PG_CHUNK;
    #pragma unroll
    for (int j = 0; j < 8; j++) {
        int idx = j * 256 + tid;
        int c2 = idx >> 10, rem = idx & 1023;
        int r = rem >> 3, i = rem & 7;
        cpa16(dst + PG_AOFF + c2 * PG_ACOPY + r * 144 + i * 16,
              g_wih16 + ((size_t)(c2 * 2048 + mbG * 128 + r)) * II + kc * 64 + i * 8);
    }
    #pragma unroll
    for (int j = 0; j < 2; j++) {
        int idx = j * 256 + tid;
        int k = idx >> 3, i = idx & 7;
        cpa16(dst + PG_BOFF + k * 144 + i * 16,
              g_x16 + ((size_t)t * 256 + kc * 64 + k) * 64 + i * 8);
    }
    CP_COMMIT();
}

__global__ void __launch_bounds__(256, 1) pregemm_mma(
    const float* __restrict__ bih, const float* __restrict__ bhh)
{
    extern __shared__ char smraw[];
    uint32_t sb0 = (uint32_t)__cvta_generic_to_shared(smraw);
    uint32_t sb  = (sb0 + 127u) & ~127u;
    char* smem = smraw + (sb - sb0);
    float* bsm = (float*)(smem + PG_BIAS);

    const int t   = blockIdx.x >> 4;
    const int mbG = blockIdx.x & 15;
    const int tid = threadIdx.x;
    const int wid = tid >> 5;
    const int lane = tid & 31;

    if (tid < 128) {
        int R = mbG * 128 + tid;
        bsm[tid] = bih[R] + bhh[R];
    }

    pg_stage(sb, 0, mbG, t, 0, tid);
    pg_stage(sb, 1, mbG, t, 1, tid);

    float d[8][4];
    #pragma unroll
    for (int i = 0; i < 8; i++)
        #pragma unroll
        for (int j = 0; j < 4; j++) d[i][j] = 0.0f;

    const uint32_t aRel = (uint32_t)(lane & 15) * 144 + (uint32_t)(lane >> 4) * 16;
    const uint32_t bRel = (uint32_t)(lane & 15) * 144 + (uint32_t)wid * 16;

    #pragma unroll
    for (int c = 0; c < 4; c++) {
        if (c < 3) CP_WAIT(1); else CP_WAIT(0);
        __syncthreads();
        uint32_t buf = sb + (c & 1) * PG_CHUNK;
        uint32_t aB = buf + PG_AOFF + aRel;
        uint32_t bB = buf + PG_BOFF + bRel;
        #pragma unroll
        for (int ks = 0; ks < 4; ks++) {
            uint32_t b0, b1;
            LDSM_X2T(b0, b1, bB + ks * 2304);
            #pragma unroll
            for (int mb = 0; mb < 8; mb++) {
                uint32_t ah0,ah1,ah2,ah3, al0,al1,al2,al3;
                LDSM_X4(ah0,ah1,ah2,ah3, aB + mb * 2304 + ks * 32);
                LDSM_X4(al0,al1,al2,al3, aB + PG_ACOPY + mb * 2304 + ks * 32);
                MMAH16816(d[mb][0],d[mb][1],d[mb][2],d[mb][3], ah0,ah1,ah2,ah3, b0,b1);
                MMAH16816(d[mb][0],d[mb][1],d[mb][2],d[mb][3], al0,al1,al2,al3, b0,b1);
            }
        }
        __syncthreads();
        if (c < 2) pg_stage(sb, c & 1, mbG, t, c + 2, tid);
    }

    float* outp = g_xgT + (size_t)t * (G4 * BB);
    const int c0 = wid * 8 + (lane & 3) * 2;
    #pragma unroll
    for (int mb = 0; mb < 8; mb++) {
        int r0 = mb * 16 + (lane >> 2);
        int R0 = mbG * 128 + r0;
        float b0 = bsm[r0], b1 = bsm[r0 + 8];
        *(float2*)(outp + (size_t)R0 * BB + c0) =
            make_float2(d[mb][0] + b0, d[mb][1] + b0);
        *(float2*)(outp + (size_t)(R0 + 8) * BB + c0) =
            make_float2(d[mb][2] + b1, d[mb][3] + b1);
    }
}

// ============================================================================
// Kernel 2: persistent fp16-HMMA recurrence, 128 CTAs x M=16.
// Flag-array grid barrier; cell update entirely in fragment registers
// (shfl_xor(16) pairs lanes holding {i,g} with lanes holding {f,o}).
// ============================================================================
#define HSM_OFF   0
#define HSM_PLANE 73728           // 512 rows * 144B
#define HSM_CHUNK 18432           // 128 rows
#define ASM_OFF   73728
#define ASM_COPY  16640           // 16 rows * 1040B
#define MBAR_OFF  107008
#define REC_SMEM  (107264 + 256)

__global__ void __launch_bounds__(256, 1) lstm_rec_mma(
    float* __restrict__ d_out, int out_size)
{
    extern __shared__ char smraw[];
    uint32_t sb0 = (uint32_t)__cvta_generic_to_shared(smraw);
    uint32_t sb  = (sb0 + 127u) & ~127u;
    char* smem = smraw + (sb - sb0);

    const int m    = blockIdx.x;
    const int tid  = threadIdx.x;
    const int wid  = tid >> 5;
    const int lane = tid & 31;

    // one-time: A tiles (fp16 hi/lo) -> smem, 1040B row stride
    for (int idx = tid; idx < 2 * 16 * 64; idx += 256) {
        int c = idx >> 10, rem = idx & 1023;
        int r = rem >> 6, i = rem & 63;
        uint4 v = *(const uint4*)(g_Awhh + ((size_t)(m*2+c)*16 + r) * HH + i*8);
        *(uint4*)(smem + ASM_OFF + c*ASM_COPY + r*1040 + i*16) = v;
    }
    // zero fp16 h ping-pong + this CTA's flag
    for (int i = m * 256 + tid; i < 9216; i += REC_CTAS * 256)
        ((uint4*)g_hf16)[i] = make_uint4(0, 0, 0, 0);
    if (tid == 0) {
        g_flags[m] = 0u;
        #pragma unroll
        for (int c = 0; c < 4; c++) MBAR_INIT(sb + MBAR_OFF + c * 8);
    }
    grid_sync_init();

    const uint32_t aBase = sb + ASM_OFF + (uint32_t)(lane & 15) * 1040
                         + (uint32_t)(lane >> 4) * 16;
    const uint32_t bBase = sb + HSM_OFF + (uint32_t)(lane & 15) * 144
                         + (uint32_t)wid * 16;

    // fragment->cell mapping (fixed across steps)
    const bool low  = (lane & 16) == 0;       // holds {i,g}; partner holds {f,o}
    const int  u    = (lane >> 2) & 3;
    const int  bcol = wid * 8 + (lane & 3) * 2 + (low ? 0 : 1);
    const int  gu   = m * 4 + u;
    const size_t xg_i = (size_t)(0*HH + gu) * BB + bcol;
    const size_t xg_f = (size_t)(1*HH + gu) * BB + bcol;
    const size_t xg_g = (size_t)(2*HH + gu) * BB + bcol;
    const size_t xg_o = (size_t)(3*HH + gu) * BB + bcol;

    float creg = 0.0f;    // cell state, register-resident
    int cur = 0;
    for (int step = 0; step < TT; step++) {
        const __half* hsrc = g_hf16 + (size_t)cur * (512 * 72);
        if (tid == 0) {
            #pragma unroll
            for (int c = 0; c < 4; c++) {
                uint32_t mb = sb + MBAR_OFF + c * 8;
                MBAR_EXPECT_TX(mb, HSM_CHUNK);
                bulk_copy(sb + HSM_OFF + c * HSM_CHUNK,
                          hsrc + (size_t)c * 128 * 72, HSM_CHUNK, mb);
            }
        }

        const float* xgs = g_xgT + (size_t)step * (G4 * BB);
        float xgi = __ldcs(xgs + xg_i);
        float xgf = __ldcs(xgs + xg_f);
        float xgg = __ldcs(xgs + xg_g);
        float xgo = __ldcs(xgs + xg_o);

        float d0 = 0.f, d1 = 0.f, d2 = 0.f, d3 = 0.f;

        #pragma unroll
        for (int c = 0; c < 4; c++) {
            mbar_wait(sb + MBAR_OFF + c * 8, step & 1);
            #pragma unroll
            for (int ks = c * 8; ks < c * 8 + 8; ks++) {
                uint32_t ah0,ah1,ah2,ah3, al0,al1,al2,al3, bh0,bh1;
                LDSM_X4(ah0,ah1,ah2,ah3, aBase + ks*32);
                LDSM_X4(al0,al1,al2,al3, aBase + ASM_COPY + ks*32);
                LDSM_X2T(bh0,bh1, bBase + ks*2304);
                MMAH16816(d0,d1,d2,d3, ah0,ah1,ah2,ah3, bh0,bh1);
                MMAH16816(d0,d1,d2,d3, al0,al1,al2,al3, bh0,bh1);
            }
        }

        // register cell update: exchange gate pairs with lane^16
        {
            float s0 = __shfl_xor_sync(0xffffffffu, d0, 16);
            float s1 = __shfl_xor_sync(0xffffffffu, d1, 16);
            float s2 = __shfl_xor_sync(0xffffffffu, d2, 16);
            float s3 = __shfl_xor_sync(0xffffffffu, d3, 16);
            float pi = (low ? d0 : s1) + xgi;
            float pf = (low ? s0 : d1) + xgf;
            float pg = (low ? d2 : s3) + xgg;
            float po = (low ? s2 : d3) + xgo;
            float ig = sigf(pi), fg = sigf(pf);
            float gg = tanhfast(pg), og = sigf(po);
            creg = fmaf(fg, creg, ig * gg);
            float h = og * tanhfast(creg);
            __stcs(&g_hsT[(size_t)step * (HH*BB) + (size_t)gu * BB + bcol], h);
            int nxt = cur ^ 1;
            g_hf16[(size_t)nxt * (512 * 72) + (size_t)gu * 72 + bcol] =
                __float2half(h);
            if (step == TT - 1 && out_size >= TT*BB*OO + 2*BB*HH) {
                d_out[TT*BB*OO + (size_t)bcol * HH + gu] = h;
                d_out[TT*BB*OO + BB*HH + (size_t)bcol * HH + gu] = creg;
            }
        }
        flag_sync(m, (unsigned)(step + 1));
        cur ^= 1;
    }
}

// ============================================================================
// Kernel 3: FC epilogue
// ============================================================================
__global__ void __launch_bounds__(320) fc_kernel(
    const float* __restrict__ fcw, const float* __restrict__ fcb,
    float* __restrict__ out)
{
    __shared__ float wsm[OO][HH];
    __shared__ float bsm[OO];
    const int t = blockIdx.x, tid = threadIdx.x;
    for (int s = tid; s < OO * HH; s += 320) wsm[s / HH][s % HH] = fcw[s];
    if (tid < OO) bsm[tid] = fcb[tid];
    __syncthreads();
    const int o = tid >> 6, b = tid & 63;
    const float* hp = g_hsT + (size_t)t * (HH * BB) + b;
    float acc = bsm[o];
    #pragma unroll 8
    for (int k = 0; k < HH; k++)
        acc = fmaf(__ldcs(hp + (size_t)k * BB), wsm[o][k], acc);
    out[(size_t)t * (BB * OO) + b * OO + o] = acc;
}

// ============================================================================
extern "C" void kernel_launch(void* const* d_in, const int* in_sizes, int n_in,
                              void* d_out, int out_size) {
    const float* x   = (const float*)d_in[0];
    const float* Wih = (const float*)d_in[1];
    const float* Whh = (const float*)d_in[2];
    const float* bih = (const float*)d_in[3];
    const float* bhh = (const float*)d_in[4];
    const float* fcw = (const float*)d_in[5];
    const float* fcb = (const float*)d_in[6];
    float* out = (float*)d_out;

    cudaFuncSetAttribute(lstm_rec_mma,
                         cudaFuncAttributeMaxDynamicSharedMemorySize, REC_SMEM);
    cudaFuncSetAttribute(pregemm_mma,
                         cudaFuncAttributeMaxDynamicSharedMemorySize, PG_SMEM);

    prep_whh<<<G4, 128>>>(Whh);
    prep_wih<<<G4, 128>>>(Wih);
    prep_x<<<TT, 256>>>(x);
    pregemm_mma<<<TT * 16, 256, PG_SMEM>>>(bih, bhh);
    lstm_rec_mma<<<REC_CTAS, 256, REC_SMEM>>>(out, out_size);
    fc_kernel<<<TT, 320>>>(fcw, fcb, out);
}